// round 15
// baseline (speedup 1.0000x reference)
#include <cuda_runtime.h>
#include <cuda_bf16.h>
#include <stdint.h>
#include <math.h>

// Problem constants
#define B_     4096
#define NSLOTS 64
#define DSLOT  1024
#define DWORK  1024
#define DIN    2048
#define H1_    512
#define H2_    256
#define M_     16

// -------------------- scratch (static device globals; no allocs) ------------
__device__ __align__(16) __nv_bfloat16 g_w1h[H1_ * DIN],  g_w1l[H1_ * DIN];
__device__ __align__(16) __nv_bfloat16 g_w2h[H2_ * H1_],  g_w2l[H2_ * H1_];
__device__ __align__(16) __nv_bfloat16 g_wmh[B_ * DWORK], g_wml[B_ * DWORK];
__device__ __align__(16) __nv_bfloat16 g_xph[B_ * DSLOT], g_xpl[B_ * DSLOT];
__device__ __align__(16) __nv_bfloat16 g_h1h[B_ * H1_],   g_h1l[B_ * H1_];
__device__ __align__(16) float g_hpre[B_ * H1_];
__device__ __align__(16) float g_h2  [B_ * H2_];
__device__ int g_cnt[32];   // per-128-row-group pool completion (0..128)
__device__ int g_wmc[32];   // per-row-group wm-tile completion   (0..8)

// -------------------- helpers ------------------------------------------------
__device__ __forceinline__ uint32_t smem_u32(const void* p) {
    uint32_t a;
    asm("{ .reg .u64 t; cvta.to.shared.u64 t, %1; cvt.u32.u64 %0, t; }" : "=r"(a) : "l"(p));
    return a;
}
__device__ __forceinline__ float gelu_exact(float v) {
    return 0.5f * v * (1.0f + erff(v * 0.70710678118654752440f));
}
#define SW128(o) ((o) ^ (((o) >> 3) & 0x70))

#define CP16(dst, src) asm volatile("cp.async.cg.shared.global [%0], [%1], 16;" :: "r"(dst), "l"(src) : "memory")
#define CP_COMMIT()    asm volatile("cp.async.commit_group;" ::: "memory")
#define CP_WAIT0()     asm volatile("cp.async.wait_group 0;" ::: "memory")
#define CP_WAIT1()     asm volatile("cp.async.wait_group 1;" ::: "memory")

__device__ __forceinline__ void ldsm4(uint32_t& r0, uint32_t& r1, uint32_t& r2, uint32_t& r3, uint32_t a) {
    asm volatile("ldmatrix.sync.aligned.m8n8.x4.shared.b16 {%0,%1,%2,%3}, [%4];"
                 : "=r"(r0), "=r"(r1), "=r"(r2), "=r"(r3) : "r"(a));
}
__device__ __forceinline__ void mma16816(float* c, const uint32_t* a, const uint32_t* b) {
    asm volatile("mma.sync.aligned.m16n8k16.row.col.f32.bf16.bf16.f32 "
                 "{%0,%1,%2,%3}, {%4,%5,%6,%7}, {%8,%9}, {%0,%1,%2,%3};"
                 : "+f"(c[0]), "+f"(c[1]), "+f"(c[2]), "+f"(c[3])
                 : "r"(a[0]), "r"(a[1]), "r"(a[2]), "r"(a[3]), "r"(b[0]), "r"(b[1]));
}

// shared inner compute: one 64-K chunk, 4 k16 steps, 3 split products
__device__ __forceinline__ void mma_chunk(uint32_t aB0, uint32_t aB1,
                                          uint32_t bB0, uint32_t bB1,
                                          float acc[2][8][4], int wid, int lane) {
    const int arow = (lane & 7) + ((lane >> 3) & 1) * 8;
    const int akb  = (lane >> 4) * 16;
    const int brow = (lane & 7) + (lane >> 4) * 8;
    const int bkb  = ((lane >> 3) & 1) * 16;
#pragma unroll
    for (int ks = 0; ks < 4; ks++) {
        const int kb = ks * 32;
        uint32_t afr[2][2][4];
        uint32_t bfr[2][8][2];
#pragma unroll
        for (int mt = 0; mt < 2; mt++) {
            uint32_t o = SW128((uint32_t)((wid * 32 + mt * 16 + arow) * 128 + kb + akb));
            ldsm4(afr[0][mt][0], afr[0][mt][1], afr[0][mt][2], afr[0][mt][3], aB0 + o);
            ldsm4(afr[1][mt][0], afr[1][mt][1], afr[1][mt][2], afr[1][mt][3], aB1 + o);
        }
#pragma unroll
        for (int ng = 0; ng < 4; ng++) {
            uint32_t o = SW128((uint32_t)((ng * 16 + brow) * 128 + kb + bkb));
            ldsm4(bfr[0][2 * ng][0], bfr[0][2 * ng][1],
                  bfr[0][2 * ng + 1][0], bfr[0][2 * ng + 1][1], bB0 + o);
            ldsm4(bfr[1][2 * ng][0], bfr[1][2 * ng][1],
                  bfr[1][2 * ng + 1][0], bfr[1][2 * ng + 1][1], bB1 + o);
        }
#pragma unroll
        for (int mt = 0; mt < 2; mt++)
#pragma unroll
            for (int nt = 0; nt < 8; nt++) {
                mma16816(acc[mt][nt], afr[0][mt], bfr[0][nt]);   // ah*bh
                mma16816(acc[mt][nt], afr[0][mt], bfr[1][nt]);   // ah*bl
                mma16816(acc[mt][nt], afr[1][mt], bfr[0][nt]);   // al*bh
            }
    }
}

// -------------------- single-buffer split-bf16 GEMM (fused kernel) -----------
template<int EPI, int ACCUM>
__device__ __forceinline__ void mma_gemm(
    const __nv_bfloat16* __restrict__ Ah, const __nv_bfloat16* __restrict__ Al, int lda,
    const __nv_bfloat16* __restrict__ Bh, const __nv_bfloat16* __restrict__ Bl, int ldb,
    int K, const float* __restrict__ bias, float* __restrict__ C, int Nc,
    int bx, int by)
{
    __shared__ __align__(1024) __nv_bfloat16 sA[2][128 * 64];
    __shared__ __align__(1024) __nv_bfloat16 sB[2][64 * 64];
    const int tid = threadIdx.x, wid = tid >> 5, lane = tid & 31;
    const uint32_t aB0 = smem_u32(sA[0]), aB1 = smem_u32(sA[1]);
    const uint32_t bB0 = smem_u32(sB[0]), bB1 = smem_u32(sB[1]);

    float acc[2][8][4];
#pragma unroll
    for (int i = 0; i < 2; i++)
#pragma unroll
        for (int j = 0; j < 8; j++)
#pragma unroll
            for (int q = 0; q < 4; q++) acc[i][j][q] = 0.f;

    const int rowA = by * 128, rowB = bx * 64;
    const int KT = K / 64;
    for (int c = 0; c < KT; c++) {
        const int k0 = c * 64;
        const char* pH = (const char*)(Ah + (size_t)(rowA + tid) * lda + k0);
        const char* pL = (const char*)(Al + (size_t)(rowA + tid) * lda + k0);
#pragma unroll
        for (int i = 0; i < 8; i++) {
            uint32_t o = SW128((uint32_t)(tid * 128 + i * 16));
            CP16(aB0 + o, pH + i * 16);
            CP16(aB1 + o, pL + i * 16);
        }
        const int rb = tid >> 1, hb = (tid & 1) * 64;
        const char* qH = (const char*)(Bh + (size_t)(rowB + rb) * ldb + k0) + hb;
        const char* qL = (const char*)(Bl + (size_t)(rowB + rb) * ldb + k0) + hb;
#pragma unroll
        for (int i = 0; i < 4; i++) {
            uint32_t o = SW128((uint32_t)(rb * 128 + hb + i * 16));
            CP16(bB0 + o, qH + i * 16);
            CP16(bB1 + o, qL + i * 16);
        }
        CP_COMMIT(); CP_WAIT0();
        __syncthreads();
        mma_chunk(aB0, aB1, bB0, bB1, acc, wid, lane);
        __syncthreads();
    }

    const int r0 = rowA + wid * 32 + lane / 4;
    const int cB = rowB + (lane % 4) * 2;
#pragma unroll
    for (int mt = 0; mt < 2; mt++)
#pragma unroll
        for (int nt = 0; nt < 8; nt++)
#pragma unroll
            for (int g = 0; g < 2; g++) {
                const int rr = r0 + mt * 16 + g * 8;
                const int cc = cB + nt * 8;
                float2 v = make_float2(acc[mt][nt][2 * g], acc[mt][nt][2 * g + 1]);
                float* p = C + (size_t)rr * Nc + cc;
                if (ACCUM) {
                    float2 pv = *reinterpret_cast<const float2*>(p);
                    v.x += pv.x; v.y += pv.y;
                } else {
                    v.x += bias[cc]; v.y += bias[cc + 1];
                }
                if (EPI) { v.x = gelu_exact(v.x); v.y = gelu_exact(v.y); }
                *reinterpret_cast<float2*>(p) = v;
            }
}

// -------------------- 2-stage pipelined split-bf16 GEMM (dynamic smem) -------
#define STAGE_BYTES 49152
template<int EPI, int ACCUM>
__device__ __forceinline__ void mma_gemm_pipe(
    const __nv_bfloat16* __restrict__ Ah, const __nv_bfloat16* __restrict__ Al, int lda,
    const __nv_bfloat16* __restrict__ Bh, const __nv_bfloat16* __restrict__ Bl, int ldb,
    int K, const float* __restrict__ bias, float* __restrict__ C, int Nc,
    int bx, int by)
{
    extern __shared__ __align__(1024) char smp[];
    const int tid = threadIdx.x, wid = tid >> 5, lane = tid & 31;
    const uint32_t base = smem_u32(smp);

    float acc[2][8][4];
#pragma unroll
    for (int i = 0; i < 2; i++)
#pragma unroll
        for (int j = 0; j < 8; j++)
#pragma unroll
            for (int q = 0; q < 4; q++) acc[i][j][q] = 0.f;

    const int rowA = by * 128, rowB = bx * 64;
    const int KT = K / 64;

    auto issue = [&](int c, int s) {
        const uint32_t sb = base + s * STAGE_BYTES;
        const uint32_t aB0 = sb, aB1 = sb + 16384, bB0 = sb + 32768, bB1 = sb + 40960;
        const int k0 = c * 64;
        const char* pH = (const char*)(Ah + (size_t)(rowA + tid) * lda + k0);
        const char* pL = (const char*)(Al + (size_t)(rowA + tid) * lda + k0);
#pragma unroll
        for (int i = 0; i < 8; i++) {
            uint32_t o = SW128((uint32_t)(tid * 128 + i * 16));
            CP16(aB0 + o, pH + i * 16);
            CP16(aB1 + o, pL + i * 16);
        }
        const int rb = tid >> 1, hb = (tid & 1) * 64;
        const char* qH = (const char*)(Bh + (size_t)(rowB + rb) * ldb + k0) + hb;
        const char* qL = (const char*)(Bl + (size_t)(rowB + rb) * ldb + k0) + hb;
#pragma unroll
        for (int i = 0; i < 4; i++) {
            uint32_t o = SW128((uint32_t)(rb * 128 + hb + i * 16));
            CP16(bB0 + o, qH + i * 16);
            CP16(bB1 + o, qL + i * 16);
        }
        CP_COMMIT();
    };

    issue(0, 0);
    for (int c = 0; c < KT; c++) {
        if (c + 1 < KT) { issue(c + 1, (c + 1) & 1); CP_WAIT1(); }
        else            { CP_WAIT0(); }
        __syncthreads();
        const uint32_t sb = base + (c & 1) * STAGE_BYTES;
        mma_chunk(sb, sb + 16384, sb + 32768, sb + 40960, acc, wid, lane);
        __syncthreads();
    }

    const int r0 = rowA + wid * 32 + lane / 4;
    const int cB = rowB + (lane % 4) * 2;
#pragma unroll
    for (int mt = 0; mt < 2; mt++)
#pragma unroll
        for (int nt = 0; nt < 8; nt++)
#pragma unroll
            for (int g = 0; g < 2; g++) {
                const int rr = r0 + mt * 16 + g * 8;
                const int cc = cB + nt * 8;
                float2 v = make_float2(acc[mt][nt][2 * g], acc[mt][nt][2 * g + 1]);
                float* p = C + (size_t)rr * Nc + cc;
                if (ACCUM) {
                    float2 pv = *reinterpret_cast<const float2*>(p);
                    v.x += pv.x; v.y += pv.y;
                } else {
                    v.x += bias[cc]; v.y += bias[cc + 1];
                }
                if (EPI) { v.x = gelu_exact(v.x); v.y = gelu_exact(v.y); }
                *reinterpret_cast<float2*>(p) = v;
            }
}

// -------------------- counter reset ------------------------------------------
__global__ void zero_cnt_k() {
    if (threadIdx.x < 32) { g_cnt[threadIdx.x] = 0; g_wmc[threadIdx.x] = 0; }
}

// -------------------- fp32 -> bf16 hi/lo split conversion --------------------
__global__ void convert_split_k(const float* __restrict__ src,
                                __nv_bfloat16* __restrict__ h, __nv_bfloat16* __restrict__ l) {
    int i = blockIdx.x * 256 + threadIdx.x;            // float4 index
    float4 v = reinterpret_cast<const float4*>(src)[i];
    __nv_bfloat16 hh[4], ll[4];
    float f[4] = {v.x, v.y, v.z, v.w};
#pragma unroll
    for (int j = 0; j < 4; j++) {
        hh[j] = __float2bfloat16(f[j]);
        ll[j] = __float2bfloat16(f[j] - __bfloat162float(hh[j]));
    }
    reinterpret_cast<uint2*>(h)[i] = *reinterpret_cast<uint2*>(hh);
    reinterpret_cast<uint2*>(l)[i] = *reinterpret_cast<uint2*>(ll);
}

// -------------------- fused: wm-GEMM | pool | slots-GEMM (tail consumers) ----
// Grid: [0,256)   wm-half GEMM1 tiles   (producers of hpre, counter g_wmc)
//       [256,4352) pool blocks          (producers of xpool, counter g_cnt)
//       [4352,4608) slots-half GEMM1 tiles (consumers; accumulate into hpre)
#define WM_BLOCKS   256
#define POOL_FIRST  256
#define SLOT_FIRST  4352

__global__ void __launch_bounds__(128)
fused_pool_wm_k(const float* __restrict__ slots,
                const float* __restrict__ b1,
                __nv_bfloat16* __restrict__ xph, __nv_bfloat16* __restrict__ xpl,
                float* __restrict__ hpre)
{
    const int gx = blockIdx.x;
    const int tid = threadIdx.x;
    if (gx < WM_BLOCKS) {
        // hpre = wm @ W1[:,1024:2048]^T + b1   (K = 1024)
        const int bx = gx & 7, by = gx >> 3;
        mma_gemm<0, 0>(g_wmh, g_wml, DWORK,
                       g_w1h + DSLOT, g_w1l + DSLOT, DIN,
                       DWORK, b1, hpre, H1_, bx, by);
        __syncthreads();
        if (tid == 0) { __threadfence(); atomicAdd(&g_wmc[by], 1); }
    } else if (gx < SLOT_FIRST) {
        // mean-pool one batch row -> bf16 hi/lo (HBM streaming)
        const int b = gx - POOL_FIRST;
        const float4* s4 = reinterpret_cast<const float4*>(slots)
                           + (size_t)b * (NSLOTS * DSLOT / 4);
        float4 a0 = make_float4(0, 0, 0, 0), a1 = a0, c0 = a0, c1 = a0;
#pragma unroll
        for (int n = 0; n < NSLOTS; n += 2) {
            float4 v0 = s4[(n + 0) * (DSLOT / 4) + tid];
            float4 w0 = s4[(n + 0) * (DSLOT / 4) + 128 + tid];
            float4 v1 = s4[(n + 1) * (DSLOT / 4) + tid];
            float4 w1 = s4[(n + 1) * (DSLOT / 4) + 128 + tid];
            a0.x += v0.x; a0.y += v0.y; a0.z += v0.z; a0.w += v0.w;
            c0.x += w0.x; c0.y += w0.y; c0.z += w0.z; c0.w += w0.w;
            a1.x += v1.x; a1.y += v1.y; a1.z += v1.z; a1.w += v1.w;
            c1.x += w1.x; c1.y += w1.y; c1.z += w1.z; c1.w += w1.w;
        }
        const float inv = 1.0f / (float)NSLOTS;
        float m0[4] = {(a0.x + a1.x) * inv, (a0.y + a1.y) * inv, (a0.z + a1.z) * inv, (a0.w + a1.w) * inv};
        float m1[4] = {(c0.x + c1.x) * inv, (c0.y + c1.y) * inv, (c0.z + c1.z) * inv, (c0.w + c1.w) * inv};
        __nv_bfloat16 hh[4], ll[4];
#pragma unroll
        for (int j = 0; j < 4; j++) {
            hh[j] = __float2bfloat16(m0[j]);
            ll[j] = __float2bfloat16(m0[j] - __bfloat162float(hh[j]));
        }
        size_t base = (size_t)b * DSLOT + tid * 4;
        *reinterpret_cast<uint2*>(&xph[base]) = *reinterpret_cast<uint2*>(hh);
        *reinterpret_cast<uint2*>(&xpl[base]) = *reinterpret_cast<uint2*>(ll);
#pragma unroll
        for (int j = 0; j < 4; j++) {
            hh[j] = __float2bfloat16(m1[j]);
            ll[j] = __float2bfloat16(m1[j] - __bfloat162float(hh[j]));
        }
        *reinterpret_cast<uint2*>(&xph[base + 512]) = *reinterpret_cast<uint2*>(hh);
        *reinterpret_cast<uint2*>(&xpl[base + 512]) = *reinterpret_cast<uint2*>(ll);
        __threadfence();
        __syncthreads();
        if (tid == 0) atomicAdd(&g_cnt[b >> 7], 1);
    } else {
        // slots-half GEMM1 tile: wait for this group's pool rows + wm tiles
        const int t = gx - SLOT_FIRST;
        const int bx = t & 7, by = t >> 3;
        if (tid == 0) {
            while (atomicAdd(&g_cnt[by], 0) < 128 || atomicAdd(&g_wmc[by], 0) < 8)
                __nanosleep(256);
            __threadfence();
        }
        __syncthreads();
        mma_gemm<0, 1>(g_xph, g_xpl, DSLOT, g_w1h, g_w1l, DIN,
                       DSLOT, nullptr, hpre, H1_, bx, by);
    }
}

// -------------------- GEMM2 (+bias+GELU, pipelined) --------------------------
__global__ void __launch_bounds__(128)
gemm2_mma_k(const float* __restrict__ b2, float* __restrict__ h2)
{
    mma_gemm_pipe<1, 0>(g_h1h, g_h1l, H1_, g_w2h, g_w2l, H1_,
                        H1_, b2, h2, H2_, blockIdx.x & 3, blockIdx.x >> 2);
}

// -------------------- LayerNorm(512) + GELU -> bf16 hi/lo --------------------
__global__ void ln_gelu_k(const float* __restrict__ hpre,
                          const float* __restrict__ gamma,
                          const float* __restrict__ beta,
                          __nv_bfloat16* __restrict__ h1h,
                          __nv_bfloat16* __restrict__ h1l) {
    int b = blockIdx.x, tid = threadIdx.x;   // 128 threads, 4 elems each
    const float4* in = reinterpret_cast<const float4*>(hpre + (size_t)b * H1_);
    float4 v = in[tid];
    float s = v.x + v.y + v.z + v.w;
    float q = v.x * v.x + v.y * v.y + v.z * v.z + v.w * v.w;
#pragma unroll
    for (int o = 16; o; o >>= 1) {
        s += __shfl_xor_sync(0xFFFFFFFFu, s, o);
        q += __shfl_xor_sync(0xFFFFFFFFu, q, o);
    }
    __shared__ float rs_[4], rq_[4];
    int w = tid >> 5;
    if ((tid & 31) == 0) { rs_[w] = s; rq_[w] = q; }
    __syncthreads();
    s = rs_[0] + rs_[1] + rs_[2] + rs_[3];
    q = rq_[0] + rq_[1] + rq_[2] + rq_[3];
    float mu   = s * (1.0f / H1_);
    float var  = q * (1.0f / H1_) - mu * mu;
    float rstd = rsqrtf(var + 1e-5f);
    float4 g  = reinterpret_cast<const float4*>(gamma)[tid];
    float4 bt = reinterpret_cast<const float4*>(beta)[tid];
    float o[4];
    o[0] = gelu_exact((v.x - mu) * rstd * g.x + bt.x);
    o[1] = gelu_exact((v.y - mu) * rstd * g.y + bt.y);
    o[2] = gelu_exact((v.z - mu) * rstd * g.z + bt.z);
    o[3] = gelu_exact((v.w - mu) * rstd * g.w + bt.w);
    __nv_bfloat16 hh[4], ll[4];
#pragma unroll
    for (int j = 0; j < 4; j++) {
        hh[j] = __float2bfloat16(o[j]);
        ll[j] = __float2bfloat16(o[j] - __bfloat162float(hh[j]));
    }
    size_t base = (size_t)b * H1_ + tid * 4;
    *reinterpret_cast<uint2*>(&h1h[base]) = *reinterpret_cast<uint2*>(hh);
    *reinterpret_cast<uint2*>(&h1l[base]) = *reinterpret_cast<uint2*>(ll);
}

// -------------------- GEMM3 + gumbel softmax ---------------------------------
__global__ void final_k(const float* __restrict__ h2, const float* __restrict__ W3,
                        const float* __restrict__ b3, const float* __restrict__ gn,
                        float* __restrict__ out) {
    int b = blockIdx.x, tid = threadIdx.x;   // 128 threads
    __shared__ float hrow[H2_];
    __shared__ float lg[M_];
    hrow[tid]       = h2[(size_t)b * H2_ + tid];
    hrow[tid + 128] = h2[(size_t)b * H2_ + tid + 128];
    __syncthreads();
    int w = tid >> 5, lane = tid & 31;
#pragma unroll
    for (int mm = 0; mm < 4; mm++) {
        int m = w * 4 + mm;
        const float* wrow = W3 + m * H2_;
        float s = 0.f;
#pragma unroll
        for (int t = lane; t < H2_; t += 32) s += hrow[t] * wrow[t];
#pragma unroll
        for (int o = 16; o; o >>= 1) s += __shfl_xor_sync(0xFFFFFFFFu, s, o);
        if (lane == 0) lg[m] = s + b3[m] + gn[(size_t)b * M_ + m];   // TAU = 1
    }
    __syncthreads();
    if (w == 0) {
        float v = (lane < M_) ? lg[lane] : -1e30f;
        float mx = v;
#pragma unroll
        for (int o = 16; o; o >>= 1) mx = fmaxf(mx, __shfl_xor_sync(0xFFFFFFFFu, mx, o));
        float e = (lane < M_) ? expf(v - mx) : 0.f;
        float ss = e;
#pragma unroll
        for (int o = 16; o; o >>= 1) ss += __shfl_xor_sync(0xFFFFFFFFu, ss, o);
        if (lane < M_) out[(size_t)b * M_ + lane] = e / ss;
    }
}

// -------------------- launch -------------------------------------------------
#define PIPE_SMEM (2 * STAGE_BYTES)   // 98304

extern "C" void kernel_launch(void* const* d_in, const int* in_sizes, int n_in,
                              void* d_out, int out_size) {
    const float* slots = (const float*)d_in[0];
    const float* wm    = (const float*)d_in[1];
    const float* gn    = (const float*)d_in[2];
    const float* W1    = (const float*)d_in[3];
    const float* b1    = (const float*)d_in[4];
    const float* gamma = (const float*)d_in[5];
    const float* beta  = (const float*)d_in[6];
    const float* W2    = (const float*)d_in[7];
    const float* b2    = (const float*)d_in[8];
    const float* W3    = (const float*)d_in[9];
    const float* b3    = (const float*)d_in[10];
    float* out = (float*)d_out;

    cudaFuncSetAttribute(gemm2_mma_k, cudaFuncAttributeMaxDynamicSharedMemorySize, PIPE_SMEM);

    __nv_bfloat16 *w1h, *w1l, *w2h, *w2l, *wmh, *wml, *xph, *xpl, *h1h, *h1l;
    float *hpre, *h2;
    cudaGetSymbolAddress((void**)&w1h, g_w1h);  cudaGetSymbolAddress((void**)&w1l, g_w1l);
    cudaGetSymbolAddress((void**)&w2h, g_w2h);  cudaGetSymbolAddress((void**)&w2l, g_w2l);
    cudaGetSymbolAddress((void**)&wmh, g_wmh);  cudaGetSymbolAddress((void**)&wml, g_wml);
    cudaGetSymbolAddress((void**)&xph, g_xph);  cudaGetSymbolAddress((void**)&xpl, g_xpl);
    cudaGetSymbolAddress((void**)&h1h, g_h1h);  cudaGetSymbolAddress((void**)&h1l, g_h1l);
    cudaGetSymbolAddress((void**)&hpre, g_hpre);
    cudaGetSymbolAddress((void**)&h2,   g_h2);

    // reset handshake counters (every call -> graph-replay deterministic)
    zero_cnt_k<<<1, 32>>>();

    // bf16 hi/lo conversions (small)
    convert_split_k<<<(H1_ * DIN)  / 1024, 256>>>(W1, w1h, w1l);
    convert_split_k<<<(H2_ * H1_)  / 1024, 256>>>(W2, w2h, w2l);
    convert_split_k<<<(B_ * DWORK) / 1024, 256>>>(wm, wmh, wml);

    // fused: wm-GEMM (256) | pool (4096) | slots-GEMM tail consumers (256)
    fused_pool_wm_k<<<4608, 128>>>(slots, b1, xph, xpl, hpre);

    // LayerNorm + GELU -> bf16 hi/lo
    ln_gelu_k<<<B_, 128>>>(hpre, gamma, beta, h1h, h1l);

    // GEMM2 (pipelined mma.sync) + bias + GELU -> h2 fp32
    gemm2_mma_k<<<(H2_ / 64) * (B_ / 128), 128, PIPE_SMEM>>>(b2, h2);

    // GEMM3 + gumbel softmax
    final_k<<<B_, 128>>>(h2, W3, b3, gn, out);
}

// round 16
// speedup vs baseline: 1.1418x; 1.1418x over previous
#include <cuda_runtime.h>
#include <cuda_bf16.h>
#include <stdint.h>
#include <math.h>

// Problem constants
#define B_     4096
#define NSLOTS 64
#define DSLOT  1024
#define DWORK  1024
#define DIN    2048
#define H1_    512
#define H2_    256
#define M_     16

// -------------------- scratch (static device globals; no allocs) ------------
__device__ __align__(16) __nv_bfloat16 g_w1h[H1_ * DIN],  g_w1l[H1_ * DIN];
__device__ __align__(16) __nv_bfloat16 g_w2h[H2_ * H1_],  g_w2l[H2_ * H1_];
__device__ __align__(16) __nv_bfloat16 g_wmh[B_ * DWORK], g_wml[B_ * DWORK];
__device__ __align__(16) __nv_bfloat16 g_xph[B_ * DSLOT], g_xpl[B_ * DSLOT];
__device__ __align__(16) __nv_bfloat16 g_h1h[B_ * H1_],   g_h1l[B_ * H1_];
__device__ __align__(16) float g_hpre[B_ * H1_];
__device__ __align__(16) float g_sp  [4][B_ * H1_];   // slots-GEMM split-K partials (32MB)
__device__ __align__(16) float g_h2p [2][B_ * H2_];   // GEMM2 split-K partials (8MB)

// -------------------- helpers ------------------------------------------------
__device__ __forceinline__ uint32_t smem_u32(const void* p) {
    uint32_t a;
    asm("{ .reg .u64 t; cvta.to.shared.u64 t, %1; cvt.u32.u64 %0, t; }" : "=r"(a) : "l"(p));
    return a;
}
__device__ __forceinline__ float gelu_exact(float v) {
    return 0.5f * v * (1.0f + erff(v * 0.70710678118654752440f));
}
#define SW128(o) ((o) ^ (((o) >> 3) & 0x70))

#define CP16(dst, src) asm volatile("cp.async.cg.shared.global [%0], [%1], 16;" :: "r"(dst), "l"(src) : "memory")
#define CP_COMMIT()    asm volatile("cp.async.commit_group;" ::: "memory")
#define CP_WAIT0()     asm volatile("cp.async.wait_group 0;" ::: "memory")
#define CP_WAIT1()     asm volatile("cp.async.wait_group 1;" ::: "memory")

__device__ __forceinline__ void ldsm4(uint32_t& r0, uint32_t& r1, uint32_t& r2, uint32_t& r3, uint32_t a) {
    asm volatile("ldmatrix.sync.aligned.m8n8.x4.shared.b16 {%0,%1,%2,%3}, [%4];"
                 : "=r"(r0), "=r"(r1), "=r"(r2), "=r"(r3) : "r"(a));
}
__device__ __forceinline__ void mma16816(float* c, const uint32_t* a, const uint32_t* b) {
    asm volatile("mma.sync.aligned.m16n8k16.row.col.f32.bf16.bf16.f32 "
                 "{%0,%1,%2,%3}, {%4,%5,%6,%7}, {%8,%9}, {%0,%1,%2,%3};"
                 : "+f"(c[0]), "+f"(c[1]), "+f"(c[2]), "+f"(c[3])
                 : "r"(a[0]), "r"(a[1]), "r"(a[2]), "r"(a[3]), "r"(b[0]), "r"(b[1]));
}

// shared inner compute: one 64-K chunk, 4 k16 steps, 3 split products
__device__ __forceinline__ void mma_chunk(uint32_t aB0, uint32_t aB1,
                                          uint32_t bB0, uint32_t bB1,
                                          float acc[2][8][4], int wid, int lane) {
    const int arow = (lane & 7) + ((lane >> 3) & 1) * 8;
    const int akb  = (lane >> 4) * 16;
    const int brow = (lane & 7) + (lane >> 4) * 8;
    const int bkb  = ((lane >> 3) & 1) * 16;
#pragma unroll
    for (int ks = 0; ks < 4; ks++) {
        const int kb = ks * 32;
        uint32_t afr[2][2][4];
        uint32_t bfr[2][8][2];
#pragma unroll
        for (int mt = 0; mt < 2; mt++) {
            uint32_t o = SW128((uint32_t)((wid * 32 + mt * 16 + arow) * 128 + kb + akb));
            ldsm4(afr[0][mt][0], afr[0][mt][1], afr[0][mt][2], afr[0][mt][3], aB0 + o);
            ldsm4(afr[1][mt][0], afr[1][mt][1], afr[1][mt][2], afr[1][mt][3], aB1 + o);
        }
#pragma unroll
        for (int ng = 0; ng < 4; ng++) {
            uint32_t o = SW128((uint32_t)((ng * 16 + brow) * 128 + kb + bkb));
            ldsm4(bfr[0][2 * ng][0], bfr[0][2 * ng][1],
                  bfr[0][2 * ng + 1][0], bfr[0][2 * ng + 1][1], bB0 + o);
            ldsm4(bfr[1][2 * ng][0], bfr[1][2 * ng][1],
                  bfr[1][2 * ng + 1][0], bfr[1][2 * ng + 1][1], bB1 + o);
        }
#pragma unroll
        for (int mt = 0; mt < 2; mt++)
#pragma unroll
            for (int nt = 0; nt < 8; nt++) {
                mma16816(acc[mt][nt], afr[0][mt], bfr[0][nt]);   // ah*bh
                mma16816(acc[mt][nt], afr[0][mt], bfr[1][nt]);   // ah*bl
                mma16816(acc[mt][nt], afr[1][mt], bfr[0][nt]);   // al*bh
            }
    }
}

// -------------------- single-buffer split-bf16 GEMM (fused kernel: wm half) --
__device__ __forceinline__ void mma_gemm_wm(
    const __nv_bfloat16* __restrict__ Ah, const __nv_bfloat16* __restrict__ Al, int lda,
    const __nv_bfloat16* __restrict__ Bh, const __nv_bfloat16* __restrict__ Bl, int ldb,
    int K, const float* __restrict__ bias, float* __restrict__ C, int Nc,
    int bx, int by)
{
    __shared__ __align__(1024) __nv_bfloat16 sA[2][128 * 64];
    __shared__ __align__(1024) __nv_bfloat16 sB[2][64 * 64];
    const int tid = threadIdx.x, wid = tid >> 5, lane = tid & 31;
    const uint32_t aB0 = smem_u32(sA[0]), aB1 = smem_u32(sA[1]);
    const uint32_t bB0 = smem_u32(sB[0]), bB1 = smem_u32(sB[1]);

    float acc[2][8][4];
#pragma unroll
    for (int i = 0; i < 2; i++)
#pragma unroll
        for (int j = 0; j < 8; j++)
#pragma unroll
            for (int q = 0; q < 4; q++) acc[i][j][q] = 0.f;

    const int rowA = by * 128, rowB = bx * 64;
    const int KT = K / 64;
    for (int c = 0; c < KT; c++) {
        const int k0 = c * 64;
        const char* pH = (const char*)(Ah + (size_t)(rowA + tid) * lda + k0);
        const char* pL = (const char*)(Al + (size_t)(rowA + tid) * lda + k0);
#pragma unroll
        for (int i = 0; i < 8; i++) {
            uint32_t o = SW128((uint32_t)(tid * 128 + i * 16));
            CP16(aB0 + o, pH + i * 16);
            CP16(aB1 + o, pL + i * 16);
        }
        const int rb = tid >> 1, hb = (tid & 1) * 64;
        const char* qH = (const char*)(Bh + (size_t)(rowB + rb) * ldb + k0) + hb;
        const char* qL = (const char*)(Bl + (size_t)(rowB + rb) * ldb + k0) + hb;
#pragma unroll
        for (int i = 0; i < 4; i++) {
            uint32_t o = SW128((uint32_t)(rb * 128 + hb + i * 16));
            CP16(bB0 + o, qH + i * 16);
            CP16(bB1 + o, qL + i * 16);
        }
        CP_COMMIT(); CP_WAIT0();
        __syncthreads();
        mma_chunk(aB0, aB1, bB0, bB1, acc, wid, lane);
        __syncthreads();
    }

    const int r0 = rowA + wid * 32 + lane / 4;
    const int cB = rowB + (lane % 4) * 2;
#pragma unroll
    for (int mt = 0; mt < 2; mt++)
#pragma unroll
        for (int nt = 0; nt < 8; nt++)
#pragma unroll
            for (int g = 0; g < 2; g++) {
                const int rr = r0 + mt * 16 + g * 8;
                const int cc = cB + nt * 8;
                float2 v = make_float2(acc[mt][nt][2 * g] + bias[cc],
                                       acc[mt][nt][2 * g + 1] + bias[cc + 1]);
                *reinterpret_cast<float2*>(&C[(size_t)rr * Nc + cc]) = v;
            }
}

// -------------------- 2-stage pipelined split-bf16 GEMM, raw-store -----------
#define STAGE_BYTES 49152
__device__ __forceinline__ void mma_gemm_pipe_raw(
    const __nv_bfloat16* __restrict__ Ah, const __nv_bfloat16* __restrict__ Al, int lda,
    const __nv_bfloat16* __restrict__ Bh, const __nv_bfloat16* __restrict__ Bl, int ldb,
    int K, float* __restrict__ C, int Nc, int bx, int by)
{
    extern __shared__ __align__(1024) char smp[];
    const int tid = threadIdx.x, wid = tid >> 5, lane = tid & 31;
    const uint32_t base = smem_u32(smp);

    float acc[2][8][4];
#pragma unroll
    for (int i = 0; i < 2; i++)
#pragma unroll
        for (int j = 0; j < 8; j++)
#pragma unroll
            for (int q = 0; q < 4; q++) acc[i][j][q] = 0.f;

    const int rowA = by * 128, rowB = bx * 64;
    const int KT = K / 64;

    auto issue = [&](int c, int s) {
        const uint32_t sb = base + s * STAGE_BYTES;
        const uint32_t aB0 = sb, aB1 = sb + 16384, bB0 = sb + 32768, bB1 = sb + 40960;
        const int k0 = c * 64;
        const char* pH = (const char*)(Ah + (size_t)(rowA + tid) * lda + k0);
        const char* pL = (const char*)(Al + (size_t)(rowA + tid) * lda + k0);
#pragma unroll
        for (int i = 0; i < 8; i++) {
            uint32_t o = SW128((uint32_t)(tid * 128 + i * 16));
            CP16(aB0 + o, pH + i * 16);
            CP16(aB1 + o, pL + i * 16);
        }
        const int rb = tid >> 1, hb = (tid & 1) * 64;
        const char* qH = (const char*)(Bh + (size_t)(rowB + rb) * ldb + k0) + hb;
        const char* qL = (const char*)(Bl + (size_t)(rowB + rb) * ldb + k0) + hb;
#pragma unroll
        for (int i = 0; i < 4; i++) {
            uint32_t o = SW128((uint32_t)(rb * 128 + hb + i * 16));
            CP16(bB0 + o, qH + i * 16);
            CP16(bB1 + o, qL + i * 16);
        }
        CP_COMMIT();
    };

    issue(0, 0);
    for (int c = 0; c < KT; c++) {
        if (c + 1 < KT) { issue(c + 1, (c + 1) & 1); CP_WAIT1(); }
        else            { CP_WAIT0(); }
        __syncthreads();
        const uint32_t sb = base + (c & 1) * STAGE_BYTES;
        mma_chunk(sb, sb + 16384, sb + 32768, sb + 40960, acc, wid, lane);
        __syncthreads();
    }

    const int r0 = rowA + wid * 32 + lane / 4;
    const int cB = rowB + (lane % 4) * 2;
#pragma unroll
    for (int mt = 0; mt < 2; mt++)
#pragma unroll
        for (int nt = 0; nt < 8; nt++)
#pragma unroll
            for (int g = 0; g < 2; g++) {
                const int rr = r0 + mt * 16 + g * 8;
                const int cc = cB + nt * 8;
                *reinterpret_cast<float2*>(&C[(size_t)rr * Nc + cc]) =
                    make_float2(acc[mt][nt][2 * g], acc[mt][nt][2 * g + 1]);
            }
}

// -------------------- merged fp32 -> bf16 hi/lo split conversions ------------
// blocks [0,1024): W1   [1024,1152): W2   [1152,5248): wm
__global__ void convert_all_k(const float* __restrict__ W1,
                              const float* __restrict__ W2,
                              const float* __restrict__ wm) {
    int gb = blockIdx.x;
    const float* src; __nv_bfloat16 *h, *l; int i;
    if (gb < 1024)      { src = W1; h = g_w1h; l = g_w1l; i = gb * 256 + threadIdx.x; }
    else if (gb < 1152) { src = W2; h = g_w2h; l = g_w2l; i = (gb - 1024) * 256 + threadIdx.x; }
    else                { src = wm; h = g_wmh; l = g_wml; i = (gb - 1152) * 256 + threadIdx.x; }
    float4 v = reinterpret_cast<const float4*>(src)[i];
    __nv_bfloat16 hh[4], ll[4];
    float f[4] = {v.x, v.y, v.z, v.w};
#pragma unroll
    for (int j = 0; j < 4; j++) {
        hh[j] = __float2bfloat16(f[j]);
        ll[j] = __float2bfloat16(f[j] - __bfloat162float(hh[j]));
    }
    reinterpret_cast<uint2*>(h)[i] = *reinterpret_cast<uint2*>(hh);
    reinterpret_cast<uint2*>(l)[i] = *reinterpret_cast<uint2*>(ll);
}

// -------------------- fused: wm-half GEMM1 (mma) + pool ----------------------
#define G1_BLOCKS 256   // 32 row-tiles x 8 col-tiles (N=512/64)

__global__ void __launch_bounds__(128)
fused_pool_wm_k(const float* __restrict__ slots,
                const float* __restrict__ b1,
                __nv_bfloat16* __restrict__ xph, __nv_bfloat16* __restrict__ xpl,
                float* __restrict__ hpre)
{
    int gx = blockIdx.x;
    if (gx < G1_BLOCKS) {
        // hpre = wm @ W1[:,1024:2048]^T + b1   (K = 1024)
        mma_gemm_wm(g_wmh, g_wml, DWORK,
                    g_w1h + DSLOT, g_w1l + DSLOT, DIN,
                    DWORK, b1, hpre, H1_, gx & 7, gx >> 3);
    } else {
        // mean-pool one batch row -> bf16 hi/lo (HBM streaming, overlaps GEMM)
        int b = gx - G1_BLOCKS;
        int tid = threadIdx.x;   // 128 threads, 8 floats each
        const float4* s4 = reinterpret_cast<const float4*>(slots)
                           + (size_t)b * (NSLOTS * DSLOT / 4);
        float4 a0 = make_float4(0, 0, 0, 0), a1 = a0, c0 = a0, c1 = a0;
#pragma unroll
        for (int n = 0; n < NSLOTS; n += 2) {
            float4 v0 = s4[(n + 0) * (DSLOT / 4) + tid];
            float4 w0 = s4[(n + 0) * (DSLOT / 4) + 128 + tid];
            float4 v1 = s4[(n + 1) * (DSLOT / 4) + tid];
            float4 w1 = s4[(n + 1) * (DSLOT / 4) + 128 + tid];
            a0.x += v0.x; a0.y += v0.y; a0.z += v0.z; a0.w += v0.w;
            c0.x += w0.x; c0.y += w0.y; c0.z += w0.z; c0.w += w0.w;
            a1.x += v1.x; a1.y += v1.y; a1.z += v1.z; a1.w += v1.w;
            c1.x += w1.x; c1.y += w1.y; c1.z += w1.z; c1.w += w1.w;
        }
        const float inv = 1.0f / (float)NSLOTS;
        float m0[4] = {(a0.x + a1.x) * inv, (a0.y + a1.y) * inv, (a0.z + a1.z) * inv, (a0.w + a1.w) * inv};
        float m1[4] = {(c0.x + c1.x) * inv, (c0.y + c1.y) * inv, (c0.z + c1.z) * inv, (c0.w + c1.w) * inv};
        __nv_bfloat16 hh[4], ll[4];
#pragma unroll
        for (int j = 0; j < 4; j++) {
            hh[j] = __float2bfloat16(m0[j]);
            ll[j] = __float2bfloat16(m0[j] - __bfloat162float(hh[j]));
        }
        size_t base = (size_t)b * DSLOT + tid * 4;
        *reinterpret_cast<uint2*>(&xph[base]) = *reinterpret_cast<uint2*>(hh);
        *reinterpret_cast<uint2*>(&xpl[base]) = *reinterpret_cast<uint2*>(ll);
#pragma unroll
        for (int j = 0; j < 4; j++) {
            hh[j] = __float2bfloat16(m1[j]);
            ll[j] = __float2bfloat16(m1[j] - __bfloat162float(hh[j]));
        }
        *reinterpret_cast<uint2*>(&xph[base + 512]) = *reinterpret_cast<uint2*>(hh);
        *reinterpret_cast<uint2*>(&xpl[base + 512]) = *reinterpret_cast<uint2*>(ll);
    }
}

// -------------------- slots-half GEMM1, split-K=4, partial buffers -----------
// grid = 1024: split s = bid>>8, tile t = bid&255 (bx=t&7, by=t>>3), KT=4 each
__global__ void __launch_bounds__(128)
gemm_slots_mma_k()
{
    const int s = blockIdx.x >> 8, t = blockIdx.x & 255;
    const int koff = s * 256;
    mma_gemm_pipe_raw(g_xph + koff, g_xpl + koff, DSLOT,
                      g_w1h + koff, g_w1l + koff, DIN,
                      256, g_sp[s], H1_, t & 7, t >> 3);
}

// -------------------- GEMM2, split-K=2, partial buffers ----------------------
// grid = 256: split s = bid>>7, tile t = bid&127 (bx=t&3, by=t>>2), KT=4 each
__global__ void __launch_bounds__(128)
gemm2_mma_k()
{
    const int s = blockIdx.x >> 7, t = blockIdx.x & 127;
    const int koff = s * 256;
    mma_gemm_pipe_raw(g_h1h + koff, g_h1l + koff, H1_,
                      g_w2h + koff, g_w2l + koff, H1_,
                      256, g_h2p[s], H2_, t & 3, t >> 2);
}

// -------------------- LN(512) + GELU: sums hpre + 4 partials -> bf16 ---------
__global__ void ln_gelu_k(const float* __restrict__ hpre,
                          const float* __restrict__ gamma,
                          const float* __restrict__ beta,
                          __nv_bfloat16* __restrict__ h1h,
                          __nv_bfloat16* __restrict__ h1l) {
    int b = blockIdx.x, tid = threadIdx.x;   // 128 threads, 4 elems each
    size_t off = (size_t)b * (H1_ / 4) + tid;
    float4 v = reinterpret_cast<const float4*>(hpre)[off];
    float4 p0 = reinterpret_cast<const float4*>(g_sp[0])[off];
    float4 p1 = reinterpret_cast<const float4*>(g_sp[1])[off];
    float4 p2 = reinterpret_cast<const float4*>(g_sp[2])[off];
    float4 p3 = reinterpret_cast<const float4*>(g_sp[3])[off];
    v.x += (p0.x + p1.x) + (p2.x + p3.x);
    v.y += (p0.y + p1.y) + (p2.y + p3.y);
    v.z += (p0.z + p1.z) + (p2.z + p3.z);
    v.w += (p0.w + p1.w) + (p2.w + p3.w);
    float s = v.x + v.y + v.z + v.w;
    float q = v.x * v.x + v.y * v.y + v.z * v.z + v.w * v.w;
#pragma unroll
    for (int o = 16; o; o >>= 1) {
        s += __shfl_xor_sync(0xFFFFFFFFu, s, o);
        q += __shfl_xor_sync(0xFFFFFFFFu, q, o);
    }
    __shared__ float rs_[4], rq_[4];
    int w = tid >> 5;
    if ((tid & 31) == 0) { rs_[w] = s; rq_[w] = q; }
    __syncthreads();
    s = rs_[0] + rs_[1] + rs_[2] + rs_[3];
    q = rq_[0] + rq_[1] + rq_[2] + rq_[3];
    float mu   = s * (1.0f / H1_);
    float var  = q * (1.0f / H1_) - mu * mu;
    float rstd = rsqrtf(var + 1e-5f);
    float4 g  = reinterpret_cast<const float4*>(gamma)[tid];
    float4 bt = reinterpret_cast<const float4*>(beta)[tid];
    float o[4];
    o[0] = gelu_exact((v.x - mu) * rstd * g.x + bt.x);
    o[1] = gelu_exact((v.y - mu) * rstd * g.y + bt.y);
    o[2] = gelu_exact((v.z - mu) * rstd * g.z + bt.z);
    o[3] = gelu_exact((v.w - mu) * rstd * g.w + bt.w);
    __nv_bfloat16 hh[4], ll[4];
#pragma unroll
    for (int j = 0; j < 4; j++) {
        hh[j] = __float2bfloat16(o[j]);
        ll[j] = __float2bfloat16(o[j] - __bfloat162float(hh[j]));
    }
    size_t base = (size_t)b * H1_ + tid * 4;
    *reinterpret_cast<uint2*>(&h1h[base]) = *reinterpret_cast<uint2*>(hh);
    *reinterpret_cast<uint2*>(&h1l[base]) = *reinterpret_cast<uint2*>(ll);
}

// -------------------- GEMM3 + gumbel softmax (sums GEMM2 partials + GELU) ----
__global__ void final_k(const float* __restrict__ W3,
                        const float* __restrict__ b2,
                        const float* __restrict__ b3, const float* __restrict__ gn,
                        float* __restrict__ out) {
    int b = blockIdx.x, tid = threadIdx.x;   // 128 threads
    __shared__ float hrow[H2_];
    __shared__ float lg[M_];
    size_t rb = (size_t)b * H2_;
#pragma unroll
    for (int e = 0; e < 2; e++) {
        int c = tid + e * 128;
        hrow[c] = gelu_exact(g_h2p[0][rb + c] + g_h2p[1][rb + c] + b2[c]);
    }
    __syncthreads();
    int w = tid >> 5, lane = tid & 31;
#pragma unroll
    for (int mm = 0; mm < 4; mm++) {
        int m = w * 4 + mm;
        const float* wrow = W3 + m * H2_;
        float s = 0.f;
#pragma unroll
        for (int t = lane; t < H2_; t += 32) s += hrow[t] * wrow[t];
#pragma unroll
        for (int o = 16; o; o >>= 1) s += __shfl_xor_sync(0xFFFFFFFFu, s, o);
        if (lane == 0) lg[m] = s + b3[m] + gn[(size_t)b * M_ + m];   // TAU = 1
    }
    __syncthreads();
    if (w == 0) {
        float v = (lane < M_) ? lg[lane] : -1e30f;
        float mx = v;
#pragma unroll
        for (int o = 16; o; o >>= 1) mx = fmaxf(mx, __shfl_xor_sync(0xFFFFFFFFu, mx, o));
        float e = (lane < M_) ? expf(v - mx) : 0.f;
        float ss = e;
#pragma unroll
        for (int o = 16; o; o >>= 1) ss += __shfl_xor_sync(0xFFFFFFFFu, ss, o);
        if (lane < M_) out[(size_t)b * M_ + lane] = e / ss;
    }
}

// -------------------- launch -------------------------------------------------
#define PIPE_SMEM (2 * STAGE_BYTES)   // 98304

extern "C" void kernel_launch(void* const* d_in, const int* in_sizes, int n_in,
                              void* d_out, int out_size) {
    const float* slots = (const float*)d_in[0];
    const float* wm    = (const float*)d_in[1];
    const float* gn    = (const float*)d_in[2];
    const float* W1    = (const float*)d_in[3];
    const float* b1    = (const float*)d_in[4];
    const float* gamma = (const float*)d_in[5];
    const float* beta  = (const float*)d_in[6];
    const float* W2    = (const float*)d_in[7];
    const float* b2    = (const float*)d_in[8];
    const float* W3    = (const float*)d_in[9];
    const float* b3    = (const float*)d_in[10];
    float* out = (float*)d_out;

    cudaFuncSetAttribute(gemm_slots_mma_k, cudaFuncAttributeMaxDynamicSharedMemorySize, PIPE_SMEM);
    cudaFuncSetAttribute(gemm2_mma_k,      cudaFuncAttributeMaxDynamicSharedMemorySize, PIPE_SMEM);

    __nv_bfloat16 *xph, *xpl, *h1h, *h1l;
    float *hpre;
    cudaGetSymbolAddress((void**)&xph, g_xph);  cudaGetSymbolAddress((void**)&xpl, g_xpl);
    cudaGetSymbolAddress((void**)&h1h, g_h1h);  cudaGetSymbolAddress((void**)&h1l, g_h1l);
    cudaGetSymbolAddress((void**)&hpre, g_hpre);

    // merged bf16 hi/lo conversions (W1 | W2 | wm in one launch)
    convert_all_k<<<5248, 256>>>(W1, W2, wm);

    // fused: wm-half GEMM1 (mma.sync, blocks 0..255) + mean-pool -> bf16 (rest)
    fused_pool_wm_k<<<G1_BLOCKS + B_, 128>>>(slots, b1, xph, xpl, hpre);

    // slots-half GEMM1: split-K=4 -> 4 partial buffers (1024 CTAs, KT=4 each)
    gemm_slots_mma_k<<<1024, 128, PIPE_SMEM>>>();

    // LayerNorm + GELU (sums hpre + 4 partials) -> bf16 hi/lo
    ln_gelu_k<<<B_, 128>>>(hpre, gamma, beta, h1h, h1l);

    // GEMM2: split-K=2 -> 2 partial buffers (256 CTAs, KT=4 each)
    gemm2_mma_k<<<256, 128, PIPE_SMEM>>>();

    // GEMM3 + gumbel softmax (applies b2 + GELU on partial sum)
    final_k<<<B_, 128>>>(W3, b2, b3, gn, out);
}

// round 17
// speedup vs baseline: 1.1582x; 1.0144x over previous
#include <cuda_runtime.h>
#include <cuda_bf16.h>
#include <stdint.h>
#include <math.h>

// Problem constants
#define B_     4096
#define NSLOTS 64
#define DSLOT  1024
#define DWORK  1024
#define DIN    2048
#define H1_    512
#define H2_    256
#define M_     16

// -------------------- scratch (static device globals; no allocs) ------------
__device__ __align__(16) __nv_bfloat16 g_w1h[H1_ * DIN],  g_w1l[H1_ * DIN];
__device__ __align__(16) __nv_bfloat16 g_w2h[H2_ * H1_],  g_w2l[H2_ * H1_];
__device__ __align__(16) __nv_bfloat16 g_wmh[B_ * DWORK], g_wml[B_ * DWORK];
__device__ __align__(16) __nv_bfloat16 g_xph[B_ * DSLOT], g_xpl[B_ * DSLOT];
__device__ __align__(16) __nv_bfloat16 g_h1h[B_ * H1_],   g_h1l[B_ * H1_];
__device__ __align__(16) float g_hpre[B_ * H1_];
__device__ __align__(16) float g_sp  [4][B_ * H1_];   // slots-GEMM split-K partials
__device__ __align__(16) float g_h2p [2][B_ * H2_];   // GEMM2 split-K partials

// -------------------- helpers ------------------------------------------------
__device__ __forceinline__ uint32_t smem_u32(const void* p) {
    uint32_t a;
    asm("{ .reg .u64 t; cvta.to.shared.u64 t, %1; cvt.u32.u64 %0, t; }" : "=r"(a) : "l"(p));
    return a;
}
__device__ __forceinline__ float gelu_exact(float v) {
    return 0.5f * v * (1.0f + erff(v * 0.70710678118654752440f));
}
#define SW128(o) ((o) ^ (((o) >> 3) & 0x70))

#define CP16(dst, src) asm volatile("cp.async.cg.shared.global [%0], [%1], 16;" :: "r"(dst), "l"(src) : "memory")
#define CP_COMMIT()    asm volatile("cp.async.commit_group;" ::: "memory")
#define CP_WAIT0()     asm volatile("cp.async.wait_group 0;" ::: "memory")

__device__ __forceinline__ void ldsm4(uint32_t& r0, uint32_t& r1, uint32_t& r2, uint32_t& r3, uint32_t a) {
    asm volatile("ldmatrix.sync.aligned.m8n8.x4.shared.b16 {%0,%1,%2,%3}, [%4];"
                 : "=r"(r0), "=r"(r1), "=r"(r2), "=r"(r3) : "r"(a));
}
__device__ __forceinline__ void mma16816(float* c, const uint32_t* a, const uint32_t* b) {
    asm volatile("mma.sync.aligned.m16n8k16.row.col.f32.bf16.bf16.f32 "
                 "{%0,%1,%2,%3}, {%4,%5,%6,%7}, {%8,%9}, {%0,%1,%2,%3};"
                 : "+f"(c[0]), "+f"(c[1]), "+f"(c[2]), "+f"(c[3])
                 : "r"(a[0]), "r"(a[1]), "r"(a[2]), "r"(a[3]), "r"(b[0]), "r"(b[1]));
}

// shared inner compute: one 64-K chunk, 4 k16 steps, 3 split products
__device__ __forceinline__ void mma_chunk(uint32_t aB0, uint32_t aB1,
                                          uint32_t bB0, uint32_t bB1,
                                          float acc[2][8][4], int wid, int lane) {
    const int arow = (lane & 7) + ((lane >> 3) & 1) * 8;
    const int akb  = (lane >> 4) * 16;
    const int brow = (lane & 7) + (lane >> 4) * 8;
    const int bkb  = ((lane >> 3) & 1) * 16;
#pragma unroll
    for (int ks = 0; ks < 4; ks++) {
        const int kb = ks * 32;
        uint32_t afr[2][2][4];
        uint32_t bfr[2][8][2];
#pragma unroll
        for (int mt = 0; mt < 2; mt++) {
            uint32_t o = SW128((uint32_t)((wid * 32 + mt * 16 + arow) * 128 + kb + akb));
            ldsm4(afr[0][mt][0], afr[0][mt][1], afr[0][mt][2], afr[0][mt][3], aB0 + o);
            ldsm4(afr[1][mt][0], afr[1][mt][1], afr[1][mt][2], afr[1][mt][3], aB1 + o);
        }
#pragma unroll
        for (int ng = 0; ng < 4; ng++) {
            uint32_t o = SW128((uint32_t)((ng * 16 + brow) * 128 + kb + bkb));
            ldsm4(bfr[0][2 * ng][0], bfr[0][2 * ng][1],
                  bfr[0][2 * ng + 1][0], bfr[0][2 * ng + 1][1], bB0 + o);
            ldsm4(bfr[1][2 * ng][0], bfr[1][2 * ng][1],
                  bfr[1][2 * ng + 1][0], bfr[1][2 * ng + 1][1], bB1 + o);
        }
#pragma unroll
        for (int mt = 0; mt < 2; mt++)
#pragma unroll
            for (int nt = 0; nt < 8; nt++) {
                mma16816(acc[mt][nt], afr[0][mt], bfr[0][nt]);   // ah*bh
                mma16816(acc[mt][nt], afr[0][mt], bfr[1][nt]);   // ah*bl
                mma16816(acc[mt][nt], afr[1][mt], bfr[0][nt]);   // al*bh
            }
    }
}

// -------------------- single-buffer split-bf16 GEMM (fused kernel: wm half) --
__device__ __forceinline__ void mma_gemm_wm(
    const __nv_bfloat16* __restrict__ Ah, const __nv_bfloat16* __restrict__ Al, int lda,
    const __nv_bfloat16* __restrict__ Bh, const __nv_bfloat16* __restrict__ Bl, int ldb,
    int K, const float* __restrict__ bias, float* __restrict__ C, int Nc,
    int bx, int by)
{
    __shared__ __align__(1024) __nv_bfloat16 sA[2][128 * 64];
    __shared__ __align__(1024) __nv_bfloat16 sB[2][64 * 64];
    const int tid = threadIdx.x, wid = tid >> 5, lane = tid & 31;
    const uint32_t aB0 = smem_u32(sA[0]), aB1 = smem_u32(sA[1]);
    const uint32_t bB0 = smem_u32(sB[0]), bB1 = smem_u32(sB[1]);

    float acc[2][8][4];
#pragma unroll
    for (int i = 0; i < 2; i++)
#pragma unroll
        for (int j = 0; j < 8; j++)
#pragma unroll
            for (int q = 0; q < 4; q++) acc[i][j][q] = 0.f;

    const int rowA = by * 128, rowB = bx * 64;
    const int KT = K / 64;
    for (int c = 0; c < KT; c++) {
        const int k0 = c * 64;
        const char* pH = (const char*)(Ah + (size_t)(rowA + tid) * lda + k0);
        const char* pL = (const char*)(Al + (size_t)(rowA + tid) * lda + k0);
#pragma unroll
        for (int i = 0; i < 8; i++) {
            uint32_t o = SW128((uint32_t)(tid * 128 + i * 16));
            CP16(aB0 + o, pH + i * 16);
            CP16(aB1 + o, pL + i * 16);
        }
        const int rb = tid >> 1, hb = (tid & 1) * 64;
        const char* qH = (const char*)(Bh + (size_t)(rowB + rb) * ldb + k0) + hb;
        const char* qL = (const char*)(Bl + (size_t)(rowB + rb) * ldb + k0) + hb;
#pragma unroll
        for (int i = 0; i < 4; i++) {
            uint32_t o = SW128((uint32_t)(rb * 128 + hb + i * 16));
            CP16(bB0 + o, qH + i * 16);
            CP16(bB1 + o, qL + i * 16);
        }
        CP_COMMIT(); CP_WAIT0();
        __syncthreads();
        mma_chunk(aB0, aB1, bB0, bB1, acc, wid, lane);
        __syncthreads();
    }

    const int r0 = rowA + wid * 32 + lane / 4;
    const int cB = rowB + (lane % 4) * 2;
#pragma unroll
    for (int mt = 0; mt < 2; mt++)
#pragma unroll
        for (int nt = 0; nt < 8; nt++)
#pragma unroll
            for (int g = 0; g < 2; g++) {
                const int rr = r0 + mt * 16 + g * 8;
                const int cc = cB + nt * 8;
                float2 v = make_float2(acc[mt][nt][2 * g] + bias[cc],
                                       acc[mt][nt][2 * g + 1] + bias[cc + 1]);
                *reinterpret_cast<float2*>(&C[(size_t)rr * Nc + cc]) = v;
            }
}

// -------------------- B-resident split-bf16 GEMM (tail kernels) --------------
// One CTA: pins its full 256-K slab of B (4 chunks, 64 rows, hi+lo = 64KB) in
// smem once, then iterates NBY row-groups of A against it. Cuts cp.async op
// count (the measured bottleneck) by eliminating per-row-group B re-loads.
// smem: B slabs [4][hi 8KB | lo 8KB] at +0 .. 64KB; A [hi 16KB | lo 16KB] at +64KB.
#define BRES_SMEM (64 * 1024 + 32 * 1024 + 1024)
template<int NBY>
__device__ __forceinline__ void mma_gemm_bres(
    const __nv_bfloat16* __restrict__ Ah, const __nv_bfloat16* __restrict__ Al, int lda,
    const __nv_bfloat16* __restrict__ Bh, const __nv_bfloat16* __restrict__ Bl, int ldb,
    int kglob, float* __restrict__ C, int Nc, int bx, int byBase)
{
    extern __shared__ char smp[];
    const int tid = threadIdx.x, wid = tid >> 5, lane = tid & 31;
    const uint32_t base = (smem_u32(smp) + 1023u) & ~1023u;
    const uint32_t sB = base, sA = base + 65536;

    const int rowB = bx * 64;
    // ---- load all 4 B slabs once ----
    {
        const int rb = tid >> 1, hb = (tid & 1) * 64;
#pragma unroll
        for (int c = 0; c < 4; c++) {
            const char* qH = (const char*)(Bh + (size_t)(rowB + rb) * ldb + kglob + c * 64) + hb;
            const char* qL = (const char*)(Bl + (size_t)(rowB + rb) * ldb + kglob + c * 64) + hb;
#pragma unroll
            for (int i = 0; i < 4; i++) {
                uint32_t o = SW128((uint32_t)(rb * 128 + hb + i * 16));
                CP16(sB + c * 16384 + o, qH + i * 16);
                CP16(sB + c * 16384 + 8192 + o, qL + i * 16);
            }
        }
        CP_COMMIT();
    }

    // ---- iterate row-groups ----
    for (int j = 0; j < NBY; j++) {
        const int rowA = (byBase + j) * 128;
        float acc[2][8][4];
#pragma unroll
        for (int i = 0; i < 2; i++)
#pragma unroll
            for (int t = 0; t < 8; t++)
#pragma unroll
                for (int q = 0; q < 4; q++) acc[i][t][q] = 0.f;

#pragma unroll
        for (int c = 0; c < 4; c++) {
            const char* pH = (const char*)(Ah + (size_t)(rowA + tid) * lda + kglob + c * 64);
            const char* pL = (const char*)(Al + (size_t)(rowA + tid) * lda + kglob + c * 64);
#pragma unroll
            for (int i = 0; i < 8; i++) {
                uint32_t o = SW128((uint32_t)(tid * 128 + i * 16));
                CP16(sA + o, pH + i * 16);
                CP16(sA + 16384 + o, pL + i * 16);
            }
            CP_COMMIT(); CP_WAIT0();     // first wait also covers the B load
            __syncthreads();
            mma_chunk(sA, sA + 16384, sB + c * 16384, sB + c * 16384 + 8192, acc, wid, lane);
            __syncthreads();             // protect sA before next chunk overwrites
        }

        const int r0 = rowA + wid * 32 + lane / 4;
        const int cB = rowB + (lane % 4) * 2;
#pragma unroll
        for (int mt = 0; mt < 2; mt++)
#pragma unroll
            for (int nt = 0; nt < 8; nt++)
#pragma unroll
                for (int g = 0; g < 2; g++) {
                    const int rr = r0 + mt * 16 + g * 8;
                    const int cc = cB + nt * 8;
                    *reinterpret_cast<float2*>(&C[(size_t)rr * Nc + cc]) =
                        make_float2(acc[mt][nt][2 * g], acc[mt][nt][2 * g + 1]);
                }
    }
}

// -------------------- merged fp32 -> bf16 hi/lo split conversions ------------
// blocks [0,1024): W1   [1024,1152): W2   [1152,5248): wm
__global__ void convert_all_k(const float* __restrict__ W1,
                              const float* __restrict__ W2,
                              const float* __restrict__ wm) {
    int gb = blockIdx.x;
    const float* src; __nv_bfloat16 *h, *l; int i;
    if (gb < 1024)      { src = W1; h = g_w1h; l = g_w1l; i = gb * 256 + threadIdx.x; }
    else if (gb < 1152) { src = W2; h = g_w2h; l = g_w2l; i = (gb - 1024) * 256 + threadIdx.x; }
    else                { src = wm; h = g_wmh; l = g_wml; i = (gb - 1152) * 256 + threadIdx.x; }
    float4 v = reinterpret_cast<const float4*>(src)[i];
    __nv_bfloat16 hh[4], ll[4];
    float f[4] = {v.x, v.y, v.z, v.w};
#pragma unroll
    for (int j = 0; j < 4; j++) {
        hh[j] = __float2bfloat16(f[j]);
        ll[j] = __float2bfloat16(f[j] - __bfloat162float(hh[j]));
    }
    reinterpret_cast<uint2*>(h)[i] = *reinterpret_cast<uint2*>(hh);
    reinterpret_cast<uint2*>(l)[i] = *reinterpret_cast<uint2*>(ll);
}

// -------------------- fused: wm-half GEMM1 (mma) + pool ----------------------
#define G1_BLOCKS 256   // 32 row-tiles x 8 col-tiles (N=512/64)

__global__ void __launch_bounds__(128)
fused_pool_wm_k(const float* __restrict__ slots,
                const float* __restrict__ b1,
                __nv_bfloat16* __restrict__ xph, __nv_bfloat16* __restrict__ xpl,
                float* __restrict__ hpre)
{
    int gx = blockIdx.x;
    if (gx < G1_BLOCKS) {
        // hpre = wm @ W1[:,1024:2048]^T + b1   (K = 1024)
        mma_gemm_wm(g_wmh, g_wml, DWORK,
                    g_w1h + DSLOT, g_w1l + DSLOT, DIN,
                    DWORK, b1, hpre, H1_, gx & 7, gx >> 3);
    } else {
        // mean-pool one batch row -> bf16 hi/lo (HBM streaming, overlaps GEMM)
        int b = gx - G1_BLOCKS;
        int tid = threadIdx.x;   // 128 threads, 8 floats each
        const float4* s4 = reinterpret_cast<const float4*>(slots)
                           + (size_t)b * (NSLOTS * DSLOT / 4);
        float4 a0 = make_float4(0, 0, 0, 0), a1 = a0, c0 = a0, c1 = a0;
#pragma unroll
        for (int n = 0; n < NSLOTS; n += 2) {
            float4 v0 = __ldcs(&s4[(n + 0) * (DSLOT / 4) + tid]);
            float4 w0 = __ldcs(&s4[(n + 0) * (DSLOT / 4) + 128 + tid]);
            float4 v1 = __ldcs(&s4[(n + 1) * (DSLOT / 4) + tid]);
            float4 w1 = __ldcs(&s4[(n + 1) * (DSLOT / 4) + 128 + tid]);
            a0.x += v0.x; a0.y += v0.y; a0.z += v0.z; a0.w += v0.w;
            c0.x += w0.x; c0.y += w0.y; c0.z += w0.z; c0.w += w0.w;
            a1.x += v1.x; a1.y += v1.y; a1.z += v1.z; a1.w += v1.w;
            c1.x += w1.x; c1.y += w1.y; c1.z += w1.z; c1.w += w1.w;
        }
        const float inv = 1.0f / (float)NSLOTS;
        float m0[4] = {(a0.x + a1.x) * inv, (a0.y + a1.y) * inv, (a0.z + a1.z) * inv, (a0.w + a1.w) * inv};
        float m1[4] = {(c0.x + c1.x) * inv, (c0.y + c1.y) * inv, (c0.z + c1.z) * inv, (c0.w + c1.w) * inv};
        __nv_bfloat16 hh[4], ll[4];
#pragma unroll
        for (int j = 0; j < 4; j++) {
            hh[j] = __float2bfloat16(m0[j]);
            ll[j] = __float2bfloat16(m0[j] - __bfloat162float(hh[j]));
        }
        size_t base = (size_t)b * DSLOT + tid * 4;
        *reinterpret_cast<uint2*>(&xph[base]) = *reinterpret_cast<uint2*>(hh);
        *reinterpret_cast<uint2*>(&xpl[base]) = *reinterpret_cast<uint2*>(ll);
#pragma unroll
        for (int j = 0; j < 4; j++) {
            hh[j] = __float2bfloat16(m1[j]);
            ll[j] = __float2bfloat16(m1[j] - __bfloat162float(hh[j]));
        }
        *reinterpret_cast<uint2*>(&xph[base + 512]) = *reinterpret_cast<uint2*>(hh);
        *reinterpret_cast<uint2*>(&xpl[base + 512]) = *reinterpret_cast<uint2*>(ll);
    }
}

// -------------------- slots-half GEMM1: B-resident, split-K=4 ----------------
// grid 256: s = bid>>6 (K slab), rem: bx = rem&7, byc = rem>>3 (8 clusters x 4 rows)
__global__ void __launch_bounds__(128)
gemm_slots_mma_k()
{
    const int s = blockIdx.x >> 6, rem = blockIdx.x & 63;
    mma_gemm_bres<4>(g_xph, g_xpl, DSLOT, g_w1h, g_w1l, DIN,
                     s * 256, g_sp[s], H1_, rem & 7, (rem >> 3) * 4);
}

// -------------------- GEMM2: B-resident, split-K=2 ---------------------------
// grid 128: s = bid>>6, rem: bx = rem&3, byc = rem>>2 (16 clusters x 2 rows)
__global__ void __launch_bounds__(128)
gemm2_mma_k()
{
    const int s = blockIdx.x >> 6, rem = blockIdx.x & 63;
    mma_gemm_bres<2>(g_h1h, g_h1l, H1_, g_w2h, g_w2l, H1_,
                     s * 256, g_h2p[s], H2_, rem & 3, (rem >> 2) * 2);
}

// -------------------- LN(512) + GELU: sums hpre + 4 partials -> bf16 ---------
__global__ void ln_gelu_k(const float* __restrict__ hpre,
                          const float* __restrict__ gamma,
                          const float* __restrict__ beta,
                          __nv_bfloat16* __restrict__ h1h,
                          __nv_bfloat16* __restrict__ h1l) {
    int b = blockIdx.x, tid = threadIdx.x;   // 128 threads, 4 elems each
    size_t off = (size_t)b * (H1_ / 4) + tid;
    float4 v = reinterpret_cast<const float4*>(hpre)[off];
    float4 p0 = reinterpret_cast<const float4*>(g_sp[0])[off];
    float4 p1 = reinterpret_cast<const float4*>(g_sp[1])[off];
    float4 p2 = reinterpret_cast<const float4*>(g_sp[2])[off];
    float4 p3 = reinterpret_cast<const float4*>(g_sp[3])[off];
    v.x += (p0.x + p1.x) + (p2.x + p3.x);
    v.y += (p0.y + p1.y) + (p2.y + p3.y);
    v.z += (p0.z + p1.z) + (p2.z + p3.z);
    v.w += (p0.w + p1.w) + (p2.w + p3.w);
    float s = v.x + v.y + v.z + v.w;
    float q = v.x * v.x + v.y * v.y + v.z * v.z + v.w * v.w;
#pragma unroll
    for (int o = 16; o; o >>= 1) {
        s += __shfl_xor_sync(0xFFFFFFFFu, s, o);
        q += __shfl_xor_sync(0xFFFFFFFFu, q, o);
    }
    __shared__ float rs_[4], rq_[4];
    int w = tid >> 5;
    if ((tid & 31) == 0) { rs_[w] = s; rq_[w] = q; }
    __syncthreads();
    s = rs_[0] + rs_[1] + rs_[2] + rs_[3];
    q = rq_[0] + rq_[1] + rq_[2] + rq_[3];
    float mu   = s * (1.0f / H1_);
    float var  = q * (1.0f / H1_) - mu * mu;
    float rstd = rsqrtf(var + 1e-5f);
    float4 g  = reinterpret_cast<const float4*>(gamma)[tid];
    float4 bt = reinterpret_cast<const float4*>(beta)[tid];
    float o[4];
    o[0] = gelu_exact((v.x - mu) * rstd * g.x + bt.x);
    o[1] = gelu_exact((v.y - mu) * rstd * g.y + bt.y);
    o[2] = gelu_exact((v.z - mu) * rstd * g.z + bt.z);
    o[3] = gelu_exact((v.w - mu) * rstd * g.w + bt.w);
    __nv_bfloat16 hh[4], ll[4];
#pragma unroll
    for (int j = 0; j < 4; j++) {
        hh[j] = __float2bfloat16(o[j]);
        ll[j] = __float2bfloat16(o[j] - __bfloat162float(hh[j]));
    }
    size_t base = (size_t)b * H1_ + tid * 4;
    *reinterpret_cast<uint2*>(&h1h[base]) = *reinterpret_cast<uint2*>(hh);
    *reinterpret_cast<uint2*>(&h1l[base]) = *reinterpret_cast<uint2*>(ll);
}

// -------------------- GEMM3 + gumbel softmax (sums GEMM2 partials + GELU) ----
__global__ void final_k(const float* __restrict__ W3,
                        const float* __restrict__ b2,
                        const float* __restrict__ b3, const float* __restrict__ gn,
                        float* __restrict__ out) {
    int b = blockIdx.x, tid = threadIdx.x;   // 128 threads
    __shared__ float hrow[H2_];
    __shared__ float lg[M_];
    size_t rb = (size_t)b * H2_;
#pragma unroll
    for (int e = 0; e < 2; e++) {
        int c = tid + e * 128;
        hrow[c] = gelu_exact(g_h2p[0][rb + c] + g_h2p[1][rb + c] + b2[c]);
    }
    __syncthreads();
    int w = tid >> 5, lane = tid & 31;
#pragma unroll
    for (int mm = 0; mm < 4; mm++) {
        int m = w * 4 + mm;
        const float* wrow = W3 + m * H2_;
        float s = 0.f;
#pragma unroll
        for (int t = lane; t < H2_; t += 32) s += hrow[t] * wrow[t];
#pragma unroll
        for (int o = 16; o; o >>= 1) s += __shfl_xor_sync(0xFFFFFFFFu, s, o);
        if (lane == 0) lg[m] = s + b3[m] + gn[(size_t)b * M_ + m];   // TAU = 1
    }
    __syncthreads();
    if (w == 0) {
        float v = (lane < M_) ? lg[lane] : -1e30f;
        float mx = v;
#pragma unroll
        for (int o = 16; o; o >>= 1) mx = fmaxf(mx, __shfl_xor_sync(0xFFFFFFFFu, mx, o));
        float e = (lane < M_) ? expf(v - mx) : 0.f;
        float ss = e;
#pragma unroll
        for (int o = 16; o; o >>= 1) ss += __shfl_xor_sync(0xFFFFFFFFu, ss, o);
        if (lane < M_) out[(size_t)b * M_ + lane] = e / ss;
    }
}

// -------------------- launch -------------------------------------------------
extern "C" void kernel_launch(void* const* d_in, const int* in_sizes, int n_in,
                              void* d_out, int out_size) {
    const float* slots = (const float*)d_in[0];
    const float* wm    = (const float*)d_in[1];
    const float* gn    = (const float*)d_in[2];
    const float* W1    = (const float*)d_in[3];
    const float* b1    = (const float*)d_in[4];
    const float* gamma = (const float*)d_in[5];
    const float* beta  = (const float*)d_in[6];
    const float* W2    = (const float*)d_in[7];
    const float* b2    = (const float*)d_in[8];
    const float* W3    = (const float*)d_in[9];
    const float* b3    = (const float*)d_in[10];
    float* out = (float*)d_out;

    cudaFuncSetAttribute(gemm_slots_mma_k, cudaFuncAttributeMaxDynamicSharedMemorySize, BRES_SMEM);
    cudaFuncSetAttribute(gemm2_mma_k,      cudaFuncAttributeMaxDynamicSharedMemorySize, BRES_SMEM);

    __nv_bfloat16 *xph, *xpl, *h1h, *h1l;
    float *hpre;
    cudaGetSymbolAddress((void**)&xph, g_xph);  cudaGetSymbolAddress((void**)&xpl, g_xpl);
    cudaGetSymbolAddress((void**)&h1h, g_h1h);  cudaGetSymbolAddress((void**)&h1l, g_h1l);
    cudaGetSymbolAddress((void**)&hpre, g_hpre);

    // merged bf16 hi/lo conversions (W1 | W2 | wm in one launch)
    convert_all_k<<<5248, 256>>>(W1, W2, wm);

    // fused: wm-half GEMM1 (mma.sync, blocks 0..255) + mean-pool -> bf16 (rest)
    fused_pool_wm_k<<<G1_BLOCKS + B_, 128>>>(slots, b1, xph, xpl, hpre);

    // slots-half GEMM1: B-resident split-K=4 (256 CTAs)
    gemm_slots_mma_k<<<256, 128, BRES_SMEM>>>();

    // LayerNorm + GELU (sums hpre + 4 partials) -> bf16 hi/lo
    ln_gelu_k<<<B_, 128>>>(hpre, gamma, beta, h1h, h1l);

    // GEMM2: B-resident split-K=2 (128 CTAs)
    gemm2_mma_k<<<128, 128, BRES_SMEM>>>();

    // GEMM3 + gumbel softmax (applies b2 + GELU on partial sum)
    final_k<<<B_, 128>>>(W3, b2, b3, gn, out);
}